// round 4
// baseline (speedup 1.0000x reference)
#include <cuda_runtime.h>
#include <cuda.h>
#include <cuda_fp16.h>
#include <cstdint>

// ===================== problem dims =====================
static constexpr int T_TOK = 8192;   // tokens (M)
static constexpr int K_DIM = 4096;   // input size (K)
static constexpr int O_DIM = 6144;   // output size (N)
static constexpr float FP8_MAX = 448.0f;

// ===================== scratch (device globals; no allocation allowed) =====================
__device__ __align__(1024) uint8_t g_xq[(size_t)T_TOK * K_DIM];   // 32 MB: e4m3(x/xs)
__device__ __align__(1024) uint8_t g_wq[(size_t)O_DIM * K_DIM];   // 24 MB: e4m3(w)
__device__ float g_xs[T_TOK];

// ===================== PTX helpers =====================
__device__ __forceinline__ uint32_t smem_u32(const void* p) {
    uint32_t a;
    asm("{ .reg .u64 t; cvta.to.shared.u64 t, %1; cvt.u32.u64 %0, t; }" : "=r"(a) : "l"(p));
    return a;
}

#define MBAR_INIT(addr, cnt) \
    asm volatile("mbarrier.init.shared.b64 [%0], %1;" :: "r"(addr), "r"(cnt) : "memory")
#define MBAR_EXPECT_TX(addr, bytes) \
    asm volatile("mbarrier.arrive.expect_tx.shared.b64 _, [%0], %1;" :: "r"(addr), "r"(bytes) : "memory")
#define MBAR_ARRIVE(addr) \
    asm volatile("mbarrier.arrive.shared.b64 _, [%0];" :: "r"(addr) : "memory")

#define MBAR_WAIT(addr, ph) do {                                                   \
    asm volatile("{\n\t.reg .pred P;\n\tWL%=:\n\t"                                 \
        "mbarrier.try_wait.parity.acquire.cta.shared::cta.b64 P, [%0], %1, 0x989680;\n\t" \
        "@P bra.uni WD%=;\n\tbra.uni WL%=;\n\tWD%=:\n\t}"                          \
        :: "r"(addr), "r"(ph) : "memory");                                         \
} while (0)

#define TMA_LOAD_3D(dst, map, cx, cy, cz, mbar) \
    asm volatile("cp.async.bulk.tensor.3d.shared::cta.global.tile.mbarrier::complete_tx::bytes " \
                 "[%0], [%1, {%2, %3, %4}], [%5];" \
                 :: "r"((uint32_t)(dst)), "l"(map), "r"((int32_t)(cx)), "r"((int32_t)(cy)), \
                    "r"((int32_t)(cz)), "r"((uint32_t)(mbar)) : "memory")

#define LDSM_X4(r0, r1, r2, r3, addr) \
    asm volatile("ldmatrix.sync.aligned.m8n8.x4.shared.b16 {%0,%1,%2,%3}, [%4];" \
                 : "=r"(r0), "=r"(r1), "=r"(r2), "=r"(r3) : "r"(addr))

// e4m3 x e4m3 -> f32 mma, accumulate in place (D == C)
#define QMMA_ACC(c, a, b0v, b1v) \
    asm volatile("mma.sync.aligned.m16n8k32.row.col.f32.e4m3.e4m3.f32 " \
                 "{%0,%1,%2,%3},{%4,%5,%6,%7},{%8,%9},{%0,%1,%2,%3};" \
                 : "+f"((c)[0]), "+f"((c)[1]), "+f"((c)[2]), "+f"((c)[3]) \
                 : "r"((a)[0]), "r"((a)[1]), "r"((a)[2]), "r"((a)[3]), "r"(b0v), "r"(b1v))

// e4m3 x e4m3 -> f32 mma, fresh accumulator (C = zeros, D written)
#define QMMA_ZC(c, a, b0v, b1v, z) \
    asm volatile("mma.sync.aligned.m16n8k32.row.col.f32.e4m3.e4m3.f32 " \
                 "{%0,%1,%2,%3},{%4,%5,%6,%7},{%8,%9},{%10,%10,%10,%10};" \
                 : "=f"((c)[0]), "=f"((c)[1]), "=f"((c)[2]), "=f"((c)[3]) \
                 : "r"((a)[0]), "r"((a)[1]), "r"((a)[2]), "r"((a)[3]), "r"(b0v), "r"(b1v), \
                   "f"(z))

__device__ __forceinline__ uint32_t swz128(uint32_t base, uint32_t off) {
    return base + (off ^ ((off >> 3) & 0x70));
}

// f32 pair -> packed e4m3x2 (byte0 = lo)
__device__ __forceinline__ uint32_t pack_e4m3_2(float lo, float hi) {
    unsigned short p;
    asm volatile("cvt.rn.satfinite.e4m3x2.f32 %0, %1, %2;" : "=h"(p) : "f"(hi), "f"(lo));
    return (uint32_t)p;
}
__device__ __forceinline__ uint32_t pack_e4m3_4(float a, float b, float c, float d) {
    return pack_e4m3_2(a, b) | (pack_e4m3_2(c, d) << 16);
}

// ===================== kernel 1: per-token quantize x -> e4m3 =====================
__global__ void __launch_bounds__(256) quant_x_kernel(const float* __restrict__ x) {
    int row = blockIdx.x;
    int t = threadIdx.x;
    const float4* xr = reinterpret_cast<const float4*>(x + (size_t)row * K_DIM);
    float4 v[4];
    float amax = 0.f;
#pragma unroll
    for (int j = 0; j < 4; ++j) {
        v[j] = xr[t + 256 * j];
        amax = fmaxf(amax, fabsf(v[j].x));
        amax = fmaxf(amax, fabsf(v[j].y));
        amax = fmaxf(amax, fabsf(v[j].z));
        amax = fmaxf(amax, fabsf(v[j].w));
    }
#pragma unroll
    for (int off = 16; off > 0; off >>= 1)
        amax = fmaxf(amax, __shfl_xor_sync(0xFFFFFFFFu, amax, off));
    __shared__ float smax[8];
    if ((t & 31) == 0) smax[t >> 5] = amax;
    __syncthreads();
    float rmax = smax[0];
#pragma unroll
    for (int j = 1; j < 8; ++j) rmax = fmaxf(rmax, smax[j]);
    float scale = fmaxf(rmax, 1e-12f) / FP8_MAX;
    if (t == 0) g_xs[row] = scale;
    uint32_t* outr = reinterpret_cast<uint32_t*>(g_xq + (size_t)row * K_DIM);
#pragma unroll
    for (int j = 0; j < 4; ++j) {
        outr[t + 256 * j] = pack_e4m3_4(v[j].x / scale, v[j].y / scale,
                                        v[j].z / scale, v[j].w / scale);
    }
}

// ===================== kernel 2: quantize weights -> e4m3 (no scale) =====================
__global__ void __launch_bounds__(256) quant_w_kernel(const float* __restrict__ w) {
    int idx4 = blockIdx.x * 256 + threadIdx.x;   // float4 index
    float4 v = reinterpret_cast<const float4*>(w)[idx4];
    reinterpret_cast<uint32_t*>(g_wq)[idx4] = pack_e4m3_4(v.x, v.y, v.z, v.w);
}

// ===================== kernel 3: fp8 GEMM with per-128K-block scale fold =====================
static constexpr int STAGES   = 4;
static constexpr int KCHUNK   = 128;              // fp8 elems per stage (=128B row)
static constexpr int K_ITERS  = K_DIM / KCHUNK;   // 32
static constexpr int CTA_M    = 128;
static constexpr int CTA_N    = 128;
static constexpr int A_STG_B  = CTA_M * 128;      // 16 KB
static constexpr int B_STG_B  = CTA_N * 128;      // 16 KB
static constexpr int SMEM_BYTES = 1024 + STAGES * (A_STG_B + B_STG_B);  // 132096

#define BAR_FULL(s)  (smem_base + 0  + (s) * 8)
#define BAR_EMPTY(s) (smem_base + 64 + (s) * 8)
#define SCALE_SM     (smem_base + 128)            // 32 floats
#define A_STAGE(s)   (smem_base + 1024 + (s) * (A_STG_B + B_STG_B))
#define B_STAGE(s)   (A_STAGE(s) + A_STG_B)

__global__ void __launch_bounds__(288, 1)
gemm_kernel(const __grid_constant__ CUtensorMap tma_a,
            const __grid_constant__ CUtensorMap tma_b,
            const float* __restrict__ wsi,
            float* __restrict__ out) {
    extern __shared__ char smem[];
    const uint32_t smem_base = smem_u32(smem);
    const int tid = threadIdx.x;
    const int wid = tid >> 5;
    const int lane = tid & 31;

    const int m_tile = blockIdx.x & 63;          // 64 M tiles
    const int n_tile = blockIdx.x >> 6;          // 48 N tiles
    const int m_cta = m_tile * CTA_M;
    const int n_cta = n_tile * CTA_N;

    if (tid == 0) {
        for (int s = 0; s < STAGES; ++s) {
            MBAR_INIT(BAR_FULL(s), 1);
            MBAR_INIT(BAR_EMPTY(s), 8);   // 8 consumer warps
        }
    }
    // per-CTA weight scales: one o-block (n_tile), all 32 k-blocks
    if (tid < K_ITERS) {
        float s = __ldg(&wsi[n_tile * K_ITERS + tid]);
        asm volatile("st.shared.f32 [%0], %1;" :: "r"(SCALE_SM + tid * 4), "f"(s));
    }
    __syncthreads();

    if (wid == 8) {
        // -------- producer (lane 0 of warp 8) --------
        if (lane == 0) {
#pragma unroll 1
            for (int i = 0; i < K_ITERS; ++i) {
                int s = i & (STAGES - 1);
                if (i >= STAGES) MBAR_WAIT(BAR_EMPTY(s), ((i >> 2) - 1) & 1);
                MBAR_EXPECT_TX(BAR_FULL(s), (uint32_t)(A_STG_B + B_STG_B));
                int k0 = i * KCHUNK;
                TMA_LOAD_3D(A_STAGE(s), &tma_a, k0, m_cta, 0, BAR_FULL(s));
                TMA_LOAD_3D(B_STAGE(s), &tma_b, k0, n_cta, 0, BAR_FULL(s));
            }
        }
    } else {
        // -------- 8 consumer warps: warp tile 64(M) x 32(N) --------
        const int warp_m = wid & 1;          // 2 M sub-tiles of 64
        const int warp_n = wid >> 1;         // 4 N sub-tiles of 32
        const int m_off = warp_m * 64;
        const int n_off = warp_n * 32;

        // ldmatrix per-lane address offsets (bytes, pre-swizzle)
        const uint32_t a_off0 = (uint32_t)(m_off + (lane & 15)) * 128 + ((lane >> 4) << 4);
        const uint32_t b_off0 = (uint32_t)(n_off + (lane & 7) + ((lane >> 4) << 3)) * 128
                              + (((lane >> 3) & 1) << 4);

        float tot[16][4];                 // 4 m16 x 4 n8 accumulators
#pragma unroll
        for (int i = 0; i < 16; ++i)
#pragma unroll
            for (int e = 0; e < 4; ++e) tot[i][e] = 0.f;

#pragma unroll 1
        for (int i = 0; i < K_ITERS; ++i) {
            int s = i & (STAGES - 1);
            MBAR_WAIT(BAR_FULL(s), (i >> 2) & 1);
            float sblk;
            asm volatile("ld.shared.f32 %0, [%1];" : "=f"(sblk) : "r"(SCALE_SM + i * 4));
            uint32_t abase = A_STAGE(s);
            uint32_t bbase = B_STAGE(s);

            float ch[16][4];              // per-128K-block fp32 chunk accumulator
#pragma unroll
            for (int ks = 0; ks < 4; ++ks) {
                uint32_t A[4][4];
                uint32_t B[4][2];
#pragma unroll
                for (int mt = 0; mt < 4; ++mt)
                    LDSM_X4(A[mt][0], A[mt][1], A[mt][2], A[mt][3],
                            swz128(abase, a_off0 + mt * (16 * 128) + ks * 32));
#pragma unroll
                for (int p = 0; p < 2; ++p)
                    LDSM_X4(B[2 * p][0], B[2 * p][1], B[2 * p + 1][0], B[2 * p + 1][1],
                            swz128(bbase, b_off0 + p * (16 * 128) + ks * 32));
#pragma unroll
                for (int mt = 0; mt < 4; ++mt)
#pragma unroll
                    for (int ng = 0; ng < 4; ++ng) {
                        if (ks == 0)
                            QMMA_ZC(ch[mt * 4 + ng], A[mt], B[ng][0], B[ng][1], 0.f);
                        else
                            QMMA_ACC(ch[mt * 4 + ng], A[mt], B[ng][0], B[ng][1]);
                    }
            }
            // fold chunk into total with this k-block's weight scale
#pragma unroll
            for (int q = 0; q < 16; ++q)
#pragma unroll
                for (int e = 0; e < 4; ++e)
                    tot[q][e] = fmaf(sblk, ch[q][e], tot[q][e]);

            if (lane == 0) MBAR_ARRIVE(BAR_EMPTY(s));
        }

        // -------- writeout: out[t, o] = tot * x_scale[t] --------
#pragma unroll
        for (int mt = 0; mt < 4; ++mt) {
            int r0 = m_cta + m_off + mt * 16 + (lane >> 2);
            int r1 = r0 + 8;
            float xs0 = g_xs[r0];
            float xs1 = g_xs[r1];
            float* p0 = out + (size_t)r0 * O_DIM + n_cta + n_off + (lane & 3) * 2;
            float* p1 = out + (size_t)r1 * O_DIM + n_cta + n_off + (lane & 3) * 2;
#pragma unroll
            for (int ng = 0; ng < 4; ++ng) {
                float2 v0 = { tot[mt * 4 + ng][0] * xs0, tot[mt * 4 + ng][1] * xs0 };
                float2 v1 = { tot[mt * 4 + ng][2] * xs1, tot[mt * 4 + ng][3] * xs1 };
                *reinterpret_cast<float2*>(p0 + ng * 8) = v0;
                *reinterpret_cast<float2*>(p1 + ng * 8) = v1;
            }
        }
    }
}

// ===================== host =====================
typedef CUresult (*EncodeFn)(CUtensorMap*, CUtensorMapDataType, cuuint32_t, void*,
                             const cuuint64_t*, const cuuint64_t*, const cuuint32_t*,
                             const cuuint32_t*, CUtensorMapInterleave, CUtensorMapSwizzle,
                             CUtensorMapL2promotion, CUtensorMapFloatOOBfill);

static EncodeFn get_encode_fn() {
    void* fn = nullptr;
    cudaDriverEntryPointQueryResult qr;
#if CUDART_VERSION >= 12050
    cudaGetDriverEntryPointByVersion("cuTensorMapEncodeTiled", &fn, 12000,
                                     cudaEnableDefault, &qr);
#else
    cudaGetDriverEntryPoint("cuTensorMapEncodeTiled", &fn, cudaEnableDefault, &qr);
#endif
    return (EncodeFn)fn;
}

static void make_map_u8(EncodeFn enc, CUtensorMap* m, void* base, uint64_t d0, uint64_t d1) {
    cuuint64_t dims[3]    = {d0, d1, 1};
    cuuint64_t strides[2] = {d0, d0 * d1};
    cuuint32_t box[3]     = {128, 128, 1};       // 128 B = SW128 atom width
    cuuint32_t es[3]      = {1, 1, 1};
    enc(m, CU_TENSOR_MAP_DATA_TYPE_UINT8, 3, base, dims, strides, box, es,
        CU_TENSOR_MAP_INTERLEAVE_NONE, CU_TENSOR_MAP_SWIZZLE_128B,
        CU_TENSOR_MAP_L2_PROMOTION_L2_128B, CU_TENSOR_MAP_FLOAT_OOB_FILL_NONE);
}

extern "C" void kernel_launch(void* const* d_in, const int* in_sizes, int n_in,
                              void* d_out, int out_size) {
    const float* x   = (const float*)d_in[0];
    const float* w   = (const float*)d_in[1];
    const float* wsi = (const float*)d_in[2];
    float* out = (float*)d_out;

    void* xq_ptr = nullptr;
    void* wq_ptr = nullptr;
    cudaGetSymbolAddress(&xq_ptr, g_xq);
    cudaGetSymbolAddress(&wq_ptr, g_wq);

    EncodeFn enc = get_encode_fn();
    CUtensorMap tma_a, tma_b;
    make_map_u8(enc, &tma_a, xq_ptr, K_DIM, T_TOK);
    make_map_u8(enc, &tma_b, wq_ptr, K_DIM, O_DIM);

    quant_x_kernel<<<T_TOK, 256>>>(x);
    quant_w_kernel<<<(O_DIM * K_DIM) / (4 * 256), 256>>>(w);

    cudaFuncSetAttribute(gemm_kernel, cudaFuncAttributeMaxDynamicSharedMemorySize, SMEM_BYTES);
    gemm_kernel<<<(T_TOK / CTA_M) * (O_DIM / CTA_N), 288, SMEM_BYTES>>>(tma_a, tma_b, wsi, out);
}